// round 16
// baseline (speedup 1.0000x reference)
#include <cuda_runtime.h>

// Problem constants
#define Bdim 4
#define Cdim 16
#define Ldim 512
#define Hdim 1024

#define DOT_TASKS 4096u   // task = 8 warps x 2 rows = 16 rows
#define DOT_BLKS  1184u   // 8 blocks/SM x 148 SM: single resident wave

// Scratch: [2][B][L][C] floats, channel contiguous. 256 KB (lives in L2).
__device__ float g_scratch[2 * Bdim * Ldim * Cdim];

// ---------------------------------------------------------------------------
// Kernel A v7: persistent grid (1184 blocks, fully resident — no wave
// transitions / tail quantization), block-level grid-stride over 4096 task
// units. Inner body is byte-identical to the proven round-2/7 loop:
// per task, warp wid handles rows 2*wid, 2*wid+1 of a 16-row chunk.
// ---------------------------------------------------------------------------
__global__ void __launch_bounds__(256, 8) dot_kernel(
    const float* __restrict__ start,
    const float* __restrict__ end,
    const float* __restrict__ v)
{
    const unsigned wid  = threadIdx.x >> 5;
    const unsigned lane = threadIdx.x & 31;

    for (unsigned task = blockIdx.x; task < DOT_TASKS; task += DOT_BLKS) {
        // task decodes exactly like round-7's (blockIdx, wid) pair:
        // global warp = task*8 + wid; tensor = gw>>14; idx0 = (gw&16383)*2
        const unsigned gw     = task * 8u + wid;
        const unsigned tensor = gw >> 14;
        const unsigned idx0   = (gw & 16383u) * 2u;

        const float* base = tensor ? end : start;
        const float4* row0 = (const float4*)(base + (size_t)idx0 * Hdim);
        const float4* row1 = (const float4*)(base + (size_t)(idx0 + 1) * Hdim);
        const float4* v4   = (const float4*)(v + tensor * Hdim);

        float sum0 = 0.f, sum1 = 0.f;
#pragma unroll
        for (int k = 0; k < Hdim / 4 / 32; k++) {    // 8 iterations
            float4 a0 = __ldcs(&row0[lane + 32 * k]);
            float4 a1 = __ldcs(&row1[lane + 32 * k]);
            float4 w  = v4[lane + 32 * k];
            sum0 += a0.x * w.x + a0.y * w.y + a0.z * w.z + a0.w * w.w;
            sum1 += a1.x * w.x + a1.y * w.y + a1.z * w.z + a1.w * w.w;
        }
#pragma unroll
        for (int o = 16; o; o >>= 1) {
            sum0 += __shfl_xor_sync(0xFFFFFFFFu, sum0, o);
            sum1 += __shfl_xor_sync(0xFFFFFFFFu, sum1, o);
        }

        if (lane == 0) {
            const unsigned b = idx0 >> 13;
            const unsigned c = (idx0 >> 9) & (Cdim - 1);
            const unsigned l = idx0 & (Ldim - 1);
            float* dst =
                &g_scratch[((tensor * Bdim + b) * Ldim + l) * Cdim + c];
            dst[0]    = sum0;
            dst[Cdim] = sum1;
        }
        // no block barrier needed: warps are independent across tasks
    }
}

// ---------------------------------------------------------------------------
// Kernel B (round-15 version, best measured): two i-tiles per block share
// one e-tile; e per-thread via direct L1-broadcast load; s via smem.
// Block covers (b, 16 i's, 64 j's, all 16 c) = 64 KB output; 1024 blocks.
// ---------------------------------------------------------------------------
__global__ void __launch_bounds__(256) add_kernel(float4* __restrict__ out)
{
    __shared__ float4 s_sm[16 * 4];   // [i][q]

    const unsigned bx = blockIdx.x;
    const unsigned jt = bx & 7;           // j tile (64 j each)
    const unsigned it = (bx >> 3) & 31;   // 16-i tile
    const unsigned b  = bx >> 8;

    const unsigned t = threadIdx.x;
    const float4* sc4 = (const float4*)g_scratch;   // [2][B][L][4] float4

    const unsigned q = t & 3;
    const unsigned j = t >> 2;                      // 0..63

    const float4 e = sc4[((Bdim + b) * Ldim + jt * 64 + j) * 4 + q];

    if (t < 64)
        s_sm[t] = sc4[(b * Ldim + it * 16) * (Cdim / 4) + t];
    __syncthreads();

    float4* dst = &out[(((b * Ldim + it * 16) * Ldim) + jt * 64 + j) * 4 + q];

#pragma unroll
    for (int i = 0; i < 16; i++) {
        float4 s = s_sm[i * 4 + q];
        dst[(size_t)i * Ldim * 4] =
            make_float4(s.x + e.x, s.y + e.y, s.z + e.z, s.w + e.w);
    }
}

extern "C" void kernel_launch(void* const* d_in, const int* in_sizes, int n_in,
                              void* d_out, int out_size)
{
    const float* start = (const float*)d_in[0];
    const float* end   = (const float*)d_in[1];
    const float* v     = (const float*)d_in[2];
    float4* out = (float4*)d_out;

    // Kernel A: persistent 1184 blocks x 256 threads, grid-stride over tasks
    dot_kernel<<<DOT_BLKS, 256>>>(start, end, v);

    // Kernel B: 4 b x 32 i-tiles x 8 j-tiles = 1024 blocks x 256 threads
    add_kernel<<<1024, 256>>>(out);
}

// round 17
// speedup vs baseline: 1.0671x; 1.0671x over previous
#include <cuda_runtime.h>

// Problem constants
#define Bdim 4
#define Cdim 16
#define Ldim 512
#define Hdim 1024

// Scratch: [2][B][L][C] floats, channel contiguous. 256 KB (lives in L2).
__device__ float g_scratch[2 * Bdim * Ldim * Cdim];

// ---------------------------------------------------------------------------
// Kernel A (proven best, rounds 2/7/15): per-row dots, 2 rows per warp.
// warp w in [0, 32768): tensor = w>>14, rows idx0 = (w & 16383)*2, idx0+1.
// __ldcs streaming keeps the 268 MB compulsory read stream out of L2's way
// (protects the L2-resident scratch + output working set).
// Measured: ~42.9 us = ~6.25 TB/s, at the read-path ceiling.
// ---------------------------------------------------------------------------
__global__ void __launch_bounds__(256) dot_kernel(
    const float* __restrict__ start,
    const float* __restrict__ end,
    const float* __restrict__ v)
{
    const unsigned warp = (blockIdx.x * blockDim.x + threadIdx.x) >> 5;
    const unsigned lane = threadIdx.x & 31;

    const unsigned tensor = warp >> 14;              // 0 or 1
    const unsigned idx0   = (warp & 16383) * 2;      // first row within tensor

    const float* base = tensor ? end : start;
    const float4* row0 = (const float4*)(base + (size_t)idx0 * Hdim);
    const float4* row1 = (const float4*)(base + (size_t)(idx0 + 1) * Hdim);
    const float4* v4   = (const float4*)(v + tensor * Hdim);

    float sum0 = 0.f, sum1 = 0.f;
#pragma unroll
    for (int k = 0; k < Hdim / 4 / 32; k++) {        // 8 iterations
        float4 a0 = __ldcs(&row0[lane + 32 * k]);
        float4 a1 = __ldcs(&row1[lane + 32 * k]);
        float4 w  = v4[lane + 32 * k];
        sum0 += a0.x * w.x + a0.y * w.y + a0.z * w.z + a0.w * w.w;
        sum1 += a1.x * w.x + a1.y * w.y + a1.z * w.z + a1.w * w.w;
    }
#pragma unroll
    for (int o = 16; o; o >>= 1) {
        sum0 += __shfl_xor_sync(0xFFFFFFFFu, sum0, o);
        sum1 += __shfl_xor_sync(0xFFFFFFFFu, sum1, o);
    }

    if (lane == 0) {
        const unsigned b = idx0 >> 13;
        const unsigned c = (idx0 >> 9) & (Cdim - 1);
        const unsigned l = idx0 & (Ldim - 1);
        float* dst = &g_scratch[((tensor * Bdim + b) * Ldim + l) * Cdim + c];
        dst[0]    = sum0;
        dst[Cdim] = sum1;
    }
}

// ---------------------------------------------------------------------------
// Kernel B (proven best, round 15): two i-tiles per block share one e-tile;
// e held per-thread in a register via direct load (4 threads/address ->
// L1 broadcast); s tile via smem. Block covers (b, 16 i's, 64 j's, 16 c)
// = 64 KB output; warp stores are 512 B fully contiguous.
// Measured: ~12.7 us = ~5.3 TB/s, at the L2 write-path ceiling.
// ---------------------------------------------------------------------------
__global__ void __launch_bounds__(256) add_kernel(float4* __restrict__ out)
{
    __shared__ float4 s_sm[16 * 4];   // [i][q]

    const unsigned bx = blockIdx.x;
    const unsigned jt = bx & 7;           // j tile (64 j each)
    const unsigned it = (bx >> 3) & 31;   // 16-i tile
    const unsigned b  = bx >> 8;

    const unsigned t = threadIdx.x;
    const float4* sc4 = (const float4*)g_scratch;   // [2][B][L][4] float4

    const unsigned q = t & 3;
    const unsigned j = t >> 2;                      // 0..63

    // e for this thread: direct load, L1-broadcast across the 4 q-threads.
    const float4 e = sc4[((Bdim + b) * Ldim + jt * 64 + j) * 4 + q];

    // s tile: 64 float4 cooperative load into smem.
    if (t < 64)
        s_sm[t] = sc4[(b * Ldim + it * 16) * (Cdim / 4) + t];
    __syncthreads();

    float4* dst = &out[(((b * Ldim + it * 16) * Ldim) + jt * 64 + j) * 4 + q];

#pragma unroll
    for (int i = 0; i < 16; i++) {
        float4 s = s_sm[i * 4 + q];
        dst[(size_t)i * Ldim * 4] =
            make_float4(s.x + e.x, s.y + e.y, s.z + e.z, s.w + e.w);
    }
}

extern "C" void kernel_launch(void* const* d_in, const int* in_sizes, int n_in,
                              void* d_out, int out_size)
{
    const float* start = (const float*)d_in[0];
    const float* end   = (const float*)d_in[1];
    const float* v     = (const float*)d_in[2];
    float4* out = (float4*)d_out;

    // Kernel A: 32768 warps (2 rows each) = 4096 blocks x 256 threads
    dot_kernel<<<4096, 256>>>(start, end, v);

    // Kernel B: 4 b x 32 i-tiles x 8 j-tiles = 1024 blocks x 256 threads
    add_kernel<<<1024, 256>>>(out);
}